// round 14
// baseline (speedup 1.0000x reference)
#include <cuda_runtime.h>
#include <cuda_fp16.h>
#include <cstdint>

// Conv2d 3x3 s1 p1 NCHW fp32: N=32,C=128,H=W=56,OC=256.
// Implicit GEMM mma.sync.m16n8k16 FP16 (fp32 accum). K' = cblk*288 + tap*32 + c.
// R14: g_in_h2 layout -> [cblk][t][pixel][16B] so prep_in phase-2 stores are
// fully coalesced (4 wf/STG instead of 32). Main loop = R12 (best known).

#define N_IMG   32
#define C_IN    128
#define H_DIM   56
#define W_DIM   56
#define OC_DIM  256
#define HW      3136
#define CHW     (C_IN * HW)
#define K_TOTAL 1152
#define M_TOTAL 100352

#define BM 128
#define BN 128
#define THREADS 256
#define NSTAGES 36                       // 4 cblk * 9 taps

#define NPIX 248                         // 128 m + halo
#define ROWB 80                          // bytes per pixel row (64 data + 16 pad)
#define ABUF_BYTES (NPIX * ROWB)         // 19840
#define B_STAGE_BYTES 8192               // 128 oc x 32 k x 2B
#define A_OFF(i) ((i) * ABUF_BYTES)
#define B_OFF(j) (2 * ABUF_BYTES + (j) * B_STAGE_BYTES)
#define OFF_ZERO (2 * ABUF_BYTES + 4 * B_STAGE_BYTES)     // 72448
#define SMEM_TOTAL (OFF_ZERO + 64)       // 72512

// [cblk(4)][t(4)][pixel(M_TOTAL)][4 words(16B)]
__device__ __align__(16) uint32_t g_in_h2[(size_t)M_TOTAL * 64];
__device__ __align__(16) uint32_t g_w_h[OC_DIM * K_TOTAL / 2];   // frag-order fp16x2

__device__ __forceinline__ uint32_t smem_u32(const void* p) {
    uint32_t a;
    asm("{ .reg .u64 t; cvta.to.shared.u64 t, %1; cvt.u32.u64 %0, t; }" : "=r"(a) : "l"(p));
    return a;
}
__device__ __forceinline__ uint32_t pack_h2(float lo, float hi) {
    __half2 h = __halves2half2(__float2half_rn(lo), __float2half_rn(hi));
    return *reinterpret_cast<uint32_t*>(&h);
}
__device__ __forceinline__ void cp16_zfill(uint32_t dst, const void* src, uint32_t sz) {
    asm volatile("cp.async.cg.shared.global [%0], [%1], 16, %2;"
                 :: "r"(dst), "l"(src), "r"(sz) : "memory");
}
__device__ __forceinline__ void cp16(uint32_t dst, const void* src) {
    asm volatile("cp.async.cg.shared.global [%0], [%1], 16;"
                 :: "r"(dst), "l"(src) : "memory");
}
__device__ __forceinline__ void lds128(uint32_t* r, uint32_t addr) {
    asm volatile("ld.shared.v4.u32 {%0,%1,%2,%3}, [%4];"
                 : "=r"(r[0]), "=r"(r[1]), "=r"(r[2]), "=r"(r[3]) : "r"(addr));
}
__device__ __forceinline__ void ldmx4(uint32_t* r, uint32_t addr) {
    asm volatile("ldmatrix.sync.aligned.m8n8.x4.shared.b16 {%0,%1,%2,%3}, [%4];"
                 : "=r"(r[0]), "=r"(r[1]), "=r"(r[2]), "=r"(r[3]) : "r"(addr));
}
__device__ __forceinline__ void mma_f16(float* c, const uint32_t* a,
                                        uint32_t b0, uint32_t b1) {
    asm volatile(
        "mma.sync.aligned.m16n8k16.row.col.f32.f16.f16.f32 "
        "{%0,%1,%2,%3}, {%4,%5,%6,%7}, {%8,%9}, {%0,%1,%2,%3};"
        : "+f"(c[0]), "+f"(c[1]), "+f"(c[2]), "+f"(c[3])
        : "r"(a[0]), "r"(a[1]), "r"(a[2]), "r"(a[3]), "r"(b0), "r"(b1));
}

// ---- prep v4: input NCHW fp32 -> [cblk][t][pixel][16B] fp16x2.
// Phase1: coalesced LDG.128 -> STS.128 (MLP=8). Phase2: conflict-free LDS.32
// (lanes span pixels -> 32 banks) + fully coalesced STG.128 (512B/warp-op).
__global__ void prep_in_kernel(const float* __restrict__ in) {
    __shared__ float sm[128][68];         // stride 68: bank(c,p) = (4c+p)%32
    const int tid = threadIdx.x;
    const int n   = blockIdx.x / 49;
    const int hw0 = (blockIdx.x - n * 49) * 64;

    const float* src = in + (size_t)n * CHW + hw0;
    #pragma unroll
    for (int i = 0; i < 8; i++) {
        const int idx = tid + 256 * i;    // [0, 2048)
        const int c   = idx >> 4;
        const int f   = idx & 15;
        const float4 v = *(const float4*)(src + (size_t)c * HW + 4 * f);
        *(float4*)&sm[c][4 * f] = v;
    }
    __syncthreads();

    const int lane = tid & 31;
    const int w    = tid >> 5;
    const int cblk = w >> 1;
    const int t0   = (w & 1) * 2;
    #pragma unroll
    for (int i = 0; i < 4; i++) {
        const int t   = t0 + (i & 1);
        const int p   = (i >> 1) * 32 + lane;     // pixel within tile
        const int cb  = cblk * 32 + 8 * t;        // first channel of this chunk
        uint32_t wds[4];
        #pragma unroll
        for (int e = 0; e < 4; e++)
            wds[e] = pack_h2(sm[cb + 2 * e][p], sm[cb + 2 * e + 1][p]);
        uint4* dst = (uint4*)(g_in_h2
                     + ((size_t)(cblk * 4 + t) * M_TOTAL + (n * HW + hw0 + p)) * 4);
        *dst = make_uint4(wds[0], wds[1], wds[2], wds[3]);
    }
}

// ---- prep: weights -> fp16x2 fragment order ----
// g_w_h layout: [s(36)][half(2)][ks(2)][wn(2)][q(4)][lane(32)][j(4)]
__global__ void prep_w_kernel(const float* __restrict__ wsrc) {
    const int idx  = blockIdx.x * blockDim.x + threadIdx.x;   // [0, 147456)
    const int s    = idx >> 12;
    const int w2   = idx & 4095;
    const int half = w2 >> 11;
    const int w    = w2 & 2047;
    const int ks   = w >> 10;
    const int wn   = (w >> 9) & 1;
    const int q    = (w >> 7) & 3;
    const int lane = (w >> 2) & 31;
    const int j    = w & 3;
    const int grp  = lane >> 2;
    const int tig  = lane & 3;
    const int oc   = half * 128 + wn * 64 + (2 * q + (j >> 1)) * 8 + grp;
    const int c0   = ks * 16 + (j & 1) * 8 + tig * 2;
    const int cblk = s / 9;
    const int rs   = s - 9 * cblk;
    const int ch   = cblk * 32 + c0;
    const float w0 = wsrc[(size_t)oc * K_TOTAL + ch * 9 + rs];
    const float w1 = wsrc[(size_t)oc * K_TOTAL + (ch + 1) * 9 + rs];
    g_w_h[idx] = pack_h2(w0, w1);
}

__global__ void __launch_bounds__(THREADS, 2)
conv2d_mma_kernel(const float* __restrict__ bias, float* __restrict__ out)
{
    extern __shared__ char smem_raw[];
    const uint32_t sbase = smem_u32(smem_raw);
    const uint32_t zaddr = sbase + OFF_ZERO;

    const int tid     = threadIdx.x;
    const int lane    = tid & 31;
    const int wid     = tid >> 5;
    const int m_base  = blockIdx.x * BM;
    const int nh      = blockIdx.y;            // oc half
    const int oc_base = nh * BN;

    if (tid < 16) ((uint32_t*)(smem_raw + OFF_ZERO))[tid] = 0u;

    // ---- A loader: 992 16B chunks (248 pixels x 4 t-chunks) ----
    auto load_A = [&](int cblk) {
        const uint32_t dbase = sbase + A_OFF(cblk & 1);
        #pragma unroll
        for (int j = 0; j < 4; j++) {
            const int ch_i = tid + 256 * j;
            if (ch_i >= NPIX * 4) break;
            const int pix = ch_i >> 2;
            const int t   = ch_i & 3;
            const int g   = m_base - 60 + pix;
            const bool ok = (g >= 0) && (g < M_TOTAL);
            const size_t gc = ok ? (size_t)g : 0;
            cp16_zfill(dbase + (uint32_t)(pix * ROWB + t * 16),
                       g_in_h2 + ((size_t)(cblk * 4 + t) * M_TOTAL + gc) * 4,
                       ok ? 16u : 0u);
        }
    };
    auto load_B = [&](int s) {
        const uint32_t dst = sbase + B_OFF(s & 3) + (uint32_t)(tid * 16);
        const uint32_t* src = g_w_h + (size_t)s * 4096 + nh * 2048 + tid * 4;
        cp16(dst, src);
        cp16(dst + 4096, src + 1024);
    };

    // ---- compute mapping: 4(M) x 2(N) warps, warp tile 32x64 ----
    const int wm  = wid & 3;
    const int wn  = wid >> 2;
    const int grp = lane >> 2;
    const int tig = lane & 3;
    const int l15 = lane & 15;
    const int khalf = lane >> 4;

    int pixloc[2], hh[2], ww[2];
    #pragma unroll
    for (int mi = 0; mi < 2; mi++) {
        const int mrow = wm * 32 + mi * 16 + l15;
        pixloc[mi] = mrow + 60;
        const int m  = m_base + mrow;
        const int nn = m / HW;
        const int hw = m - nn * HW;
        hh[mi] = hw / W_DIM;
        ww[mi] = hw - hh[mi] * W_DIM;
    }

    float acc[2][8][4];
    #pragma unroll
    for (int mi = 0; mi < 2; mi++)
        #pragma unroll
        for (int ni = 0; ni < 8; ni++)
            #pragma unroll
            for (int q = 0; q < 4; q++) acc[mi][ni][q] = 0.0f;

    load_A(0); load_B(0);
    asm volatile("cp.async.commit_group;" ::: "memory");
    load_A(1); load_B(1);
    asm volatile("cp.async.commit_group;" ::: "memory");
    load_B(2);
    asm volatile("cp.async.commit_group;" ::: "memory");

    int tap = 0, cblk = 0, dh = -1, dw = -1;
    for (int s = 0; s < NSTAGES; s++) {
        asm volatile("cp.async.wait_group 2;" ::: "memory");
        __syncthreads();

        // issue next loads into the MMA shadow (buffers last read at s-1)
        if (s + 3 < NSTAGES) load_B(s + 3);
        if (tap == 0 && cblk < 3) load_A(cblk + 1);
        asm volatile("cp.async.commit_group;" ::: "memory");

        const uint32_t Ab = sbase + A_OFF(cblk & 1);
        const uint32_t Bb = sbase + B_OFF(s & 3);
        const int shift = dh * W_DIM + dw;

        uint32_t ra[2];
        #pragma unroll
        for (int mi = 0; mi < 2; mi++) {
            const bool ok = ((unsigned)(hh[mi] + dh) < (unsigned)H_DIM) &&
                            ((unsigned)(ww[mi] + dw) < (unsigned)W_DIM);
            ra[mi] = ok ? (Ab + (uint32_t)((pixloc[mi] + shift) * ROWB + khalf * 16))
                        : zaddr;
        }

        const uint32_t bb_base = Bb + (uint32_t)(wn * 2048 + lane * 16);
        #pragma unroll
        for (int ks = 0; ks < 2; ks++) {
            uint32_t a[2][4];
            ldmx4(a[0], ra[0] + ks * 32);
            ldmx4(a[1], ra[1] + ks * 32);
            uint32_t bb[4][4];
            #pragma unroll
            for (int q = 0; q < 4; q++)
                lds128(bb[q], bb_base + (uint32_t)(ks * 4096 + q * 512));
            #pragma unroll
            for (int q = 0; q < 4; q++)
                #pragma unroll
                for (int sb = 0; sb < 2; sb++) {
                    const int ni = q * 2 + sb;
                    #pragma unroll
                    for (int mi = 0; mi < 2; mi++)
                        mma_f16(acc[mi][ni], a[mi],
                                bb[q][sb * 2], bb[q][sb * 2 + 1]);
                }
        }

        if (++tap == 9) { tap = 0; cblk++; dh = -1; dw = -1; }
        else { if (++dw == 2) { dw = -1; dh++; } }
    }

    // ---- epilogue: +bias, scatter to NCHW ----
    #pragma unroll
    for (int mi = 0; mi < 2; mi++) {
        #pragma unroll
        for (int hf = 0; hf < 2; hf++) {
            const int m   = m_base + wm * 32 + mi * 16 + grp + 8 * hf;
            const int nn  = m / HW;
            const int phw = m - nn * HW;
            float* op = out + (size_t)nn * OC_DIM * HW + phw;
            #pragma unroll
            for (int ni = 0; ni < 8; ni++) {
                const int oc = oc_base + wn * 64 + ni * 8 + 2 * tig;
                const float b0 = __ldg(bias + oc);
                const float b1 = __ldg(bias + oc + 1);
                op[(size_t)oc * HW]       = acc[mi][ni][2 * hf + 0] + b0;
                op[(size_t)(oc + 1) * HW] = acc[mi][ni][2 * hf + 1] + b1;
            }
        }
    }
}

extern "C" void kernel_launch(void* const* d_in, const int* in_sizes, int n_in,
                              void* d_out, int out_size)
{
    const float* in   = (const float*)d_in[0];
    const float* wgt  = (const float*)d_in[1];
    const float* bias = (const float*)d_in[2];
    float* out        = (float*)d_out;

    prep_in_kernel<<<32 * 49, 256>>>(in);
    prep_w_kernel<<<(OC_DIM * K_TOTAL / 2) / 256, 256>>>(wgt);

    cudaFuncSetAttribute(conv2d_mma_kernel,
                         cudaFuncAttributeMaxDynamicSharedMemorySize, SMEM_TOTAL);
    dim3 grid(M_TOTAL / BM, OC_DIM / BN, 1);   // 784 x 2
    conv2d_mma_kernel<<<grid, THREADS, SMEM_TOTAL>>>(bias, out);
}

// round 15
// speedup vs baseline: 1.0233x; 1.0233x over previous
#include <cuda_runtime.h>
#include <cuda_fp16.h>
#include <cstdint>

// Conv2d 3x3 s1 p1 NCHW fp32: N=32,C=128,H=W=56,OC=256.
// Implicit GEMM mma.sync.m16n8k16 FP16 (fp32 accum). K' = cblk*288 + tap*32 + c.
// R15: g_in_h2 layout [cblk][pixel][64B] — main A-loads are 512B-contiguous
// per warp within one plane AND prep_in stores stay fully coalesced.
// Main loop = R12 (single sync, 4-deep B ring).

#define N_IMG   32
#define C_IN    128
#define H_DIM   56
#define W_DIM   56
#define OC_DIM  256
#define HW      3136
#define CHW     (C_IN * HW)
#define K_TOTAL 1152
#define M_TOTAL 100352

#define BM 128
#define BN 128
#define THREADS 256
#define NSTAGES 36                       // 4 cblk * 9 taps

#define NPIX 248                         // 128 m + halo
#define ROWB 80                          // bytes per pixel row (64 data + 16 pad)
#define ABUF_BYTES (NPIX * ROWB)         // 19840
#define B_STAGE_BYTES 8192               // 128 oc x 32 k x 2B
#define A_OFF(i) ((i) * ABUF_BYTES)
#define B_OFF(j) (2 * ABUF_BYTES + (j) * B_STAGE_BYTES)
#define OFF_ZERO (2 * ABUF_BYTES + 4 * B_STAGE_BYTES)     // 72448
#define SMEM_TOTAL (OFF_ZERO + 64)       // 72512

// [cblk(4)][pixel(M_TOTAL)][16 words(64B)]
__device__ __align__(16) uint32_t g_in_h2[(size_t)M_TOTAL * 64];
__device__ __align__(16) uint32_t g_w_h[OC_DIM * K_TOTAL / 2];   // frag-order fp16x2

__device__ __forceinline__ uint32_t smem_u32(const void* p) {
    uint32_t a;
    asm("{ .reg .u64 t; cvta.to.shared.u64 t, %1; cvt.u32.u64 %0, t; }" : "=r"(a) : "l"(p));
    return a;
}
__device__ __forceinline__ uint32_t pack_h2(float lo, float hi) {
    __half2 h = __halves2half2(__float2half_rn(lo), __float2half_rn(hi));
    return *reinterpret_cast<uint32_t*>(&h);
}
__device__ __forceinline__ void cp16_zfill(uint32_t dst, const void* src, uint32_t sz) {
    asm volatile("cp.async.cg.shared.global [%0], [%1], 16, %2;"
                 :: "r"(dst), "l"(src), "r"(sz) : "memory");
}
__device__ __forceinline__ void cp16(uint32_t dst, const void* src) {
    asm volatile("cp.async.cg.shared.global [%0], [%1], 16;"
                 :: "r"(dst), "l"(src) : "memory");
}
__device__ __forceinline__ void lds128(uint32_t* r, uint32_t addr) {
    asm volatile("ld.shared.v4.u32 {%0,%1,%2,%3}, [%4];"
                 : "=r"(r[0]), "=r"(r[1]), "=r"(r[2]), "=r"(r[3]) : "r"(addr));
}
__device__ __forceinline__ void ldmx4(uint32_t* r, uint32_t addr) {
    asm volatile("ldmatrix.sync.aligned.m8n8.x4.shared.b16 {%0,%1,%2,%3}, [%4];"
                 : "=r"(r[0]), "=r"(r[1]), "=r"(r[2]), "=r"(r[3]) : "r"(addr));
}
__device__ __forceinline__ void mma_f16(float* c, const uint32_t* a,
                                        uint32_t b0, uint32_t b1) {
    asm volatile(
        "mma.sync.aligned.m16n8k16.row.col.f32.f16.f16.f32 "
        "{%0,%1,%2,%3}, {%4,%5,%6,%7}, {%8,%9}, {%0,%1,%2,%3};"
        : "+f"(c[0]), "+f"(c[1]), "+f"(c[2]), "+f"(c[3])
        : "r"(a[0]), "r"(a[1]), "r"(a[2]), "r"(a[3]), "r"(b0), "r"(b1));
}

// ---- prep v5: input NCHW fp32 -> [cblk][pixel][64B] fp16x2.
// Phase1: coalesced LDG.128 -> STS.128 (MLP=8). Phase2: lane -> (p,t) chunk,
// warp stores 512B contiguous (4 wf/STG). 4-way LDS conflict accepted.
__global__ void prep_in_kernel(const float* __restrict__ in) {
    __shared__ float sm[128][68];
    const int tid = threadIdx.x;
    const int n   = blockIdx.x / 49;
    const int hw0 = (blockIdx.x - n * 49) * 64;

    const float* src = in + (size_t)n * CHW + hw0;
    #pragma unroll
    for (int i = 0; i < 8; i++) {
        const int idx = tid + 256 * i;    // [0, 2048)
        const int c   = idx >> 4;
        const int f   = idx & 15;
        const float4 v = *(const float4*)(src + (size_t)c * HW + 4 * f);
        *(float4*)&sm[c][4 * f] = v;
    }
    __syncthreads();

    const int p = tid >> 2;               // pixel within tile (0..63)
    const int t = tid & 3;                // 16B chunk within pixel
    #pragma unroll
    for (int cblk = 0; cblk < 4; cblk++) {
        const int cb = cblk * 32 + 8 * t;
        uint32_t wds[4];
        #pragma unroll
        for (int e = 0; e < 4; e++)
            wds[e] = pack_h2(sm[cb + 2 * e][p], sm[cb + 2 * e + 1][p]);
        uint4* dst = (uint4*)(g_in_h2
                     + ((size_t)cblk * M_TOTAL + (n * HW + hw0 + p)) * 16 + t * 4);
        *dst = make_uint4(wds[0], wds[1], wds[2], wds[3]);
    }
}

// ---- prep: weights -> fp16x2 fragment order ----
// g_w_h layout: [s(36)][half(2)][ks(2)][wn(2)][q(4)][lane(32)][j(4)]
__global__ void prep_w_kernel(const float* __restrict__ wsrc) {
    const int idx  = blockIdx.x * blockDim.x + threadIdx.x;   // [0, 147456)
    const int s    = idx >> 12;
    const int w2   = idx & 4095;
    const int half = w2 >> 11;
    const int w    = w2 & 2047;
    const int ks   = w >> 10;
    const int wn   = (w >> 9) & 1;
    const int q    = (w >> 7) & 3;
    const int lane = (w >> 2) & 31;
    const int j    = w & 3;
    const int grp  = lane >> 2;
    const int tig  = lane & 3;
    const int oc   = half * 128 + wn * 64 + (2 * q + (j >> 1)) * 8 + grp;
    const int c0   = ks * 16 + (j & 1) * 8 + tig * 2;
    const int cblk = s / 9;
    const int rs   = s - 9 * cblk;
    const int ch   = cblk * 32 + c0;
    const float w0 = wsrc[(size_t)oc * K_TOTAL + ch * 9 + rs];
    const float w1 = wsrc[(size_t)oc * K_TOTAL + (ch + 1) * 9 + rs];
    g_w_h[idx] = pack_h2(w0, w1);
}

__global__ void __launch_bounds__(THREADS, 2)
conv2d_mma_kernel(const float* __restrict__ bias, float* __restrict__ out)
{
    extern __shared__ char smem_raw[];
    const uint32_t sbase = smem_u32(smem_raw);
    const uint32_t zaddr = sbase + OFF_ZERO;

    const int tid     = threadIdx.x;
    const int lane    = tid & 31;
    const int wid     = tid >> 5;
    const int m_base  = blockIdx.x * BM;
    const int nh      = blockIdx.y;            // oc half
    const int oc_base = nh * BN;

    if (tid < 16) ((uint32_t*)(smem_raw + OFF_ZERO))[tid] = 0u;

    // ---- A loader: 992 16B chunks; warp reads 512B contiguous per plane ----
    auto load_A = [&](int cblk) {
        const uint32_t dbase = sbase + A_OFF(cblk & 1);
        const uint32_t* plane = g_in_h2 + (size_t)cblk * M_TOTAL * 16;
        #pragma unroll
        for (int j = 0; j < 4; j++) {
            const int ch_i = tid + 256 * j;
            if (ch_i >= NPIX * 4) break;
            const int pix = ch_i >> 2;
            const int t   = ch_i & 3;
            const int g   = m_base - 60 + pix;
            const bool ok = (g >= 0) && (g < M_TOTAL);
            const size_t gc = ok ? (size_t)g : 0;
            cp16_zfill(dbase + (uint32_t)(pix * ROWB + t * 16),
                       plane + gc * 16 + t * 4,
                       ok ? 16u : 0u);
        }
    };
    auto load_B = [&](int s) {
        const uint32_t dst = sbase + B_OFF(s & 3) + (uint32_t)(tid * 16);
        const uint32_t* src = g_w_h + (size_t)s * 4096 + nh * 2048 + tid * 4;
        cp16(dst, src);
        cp16(dst + 4096, src + 1024);
    };

    // ---- compute mapping: 4(M) x 2(N) warps, warp tile 32x64 ----
    const int wm  = wid & 3;
    const int wn  = wid >> 2;
    const int grp = lane >> 2;
    const int tig = lane & 3;
    const int l15 = lane & 15;
    const int khalf = lane >> 4;

    int pixloc[2], hh[2], ww[2];
    #pragma unroll
    for (int mi = 0; mi < 2; mi++) {
        const int mrow = wm * 32 + mi * 16 + l15;
        pixloc[mi] = mrow + 60;
        const int m  = m_base + mrow;
        const int nn = m / HW;
        const int hw = m - nn * HW;
        hh[mi] = hw / W_DIM;
        ww[mi] = hw - hh[mi] * W_DIM;
    }

    float acc[2][8][4];
    #pragma unroll
    for (int mi = 0; mi < 2; mi++)
        #pragma unroll
        for (int ni = 0; ni < 8; ni++)
            #pragma unroll
            for (int q = 0; q < 4; q++) acc[mi][ni][q] = 0.0f;

    load_A(0); load_B(0);
    asm volatile("cp.async.commit_group;" ::: "memory");
    load_A(1); load_B(1);
    asm volatile("cp.async.commit_group;" ::: "memory");
    load_B(2);
    asm volatile("cp.async.commit_group;" ::: "memory");

    int tap = 0, cblk = 0, dh = -1, dw = -1;
    for (int s = 0; s < NSTAGES; s++) {
        asm volatile("cp.async.wait_group 2;" ::: "memory");
        __syncthreads();

        // issue next loads into the MMA shadow (buffers last read at s-1)
        if (s + 3 < NSTAGES) load_B(s + 3);
        if (tap == 0 && cblk < 3) load_A(cblk + 1);
        asm volatile("cp.async.commit_group;" ::: "memory");

        const uint32_t Ab = sbase + A_OFF(cblk & 1);
        const uint32_t Bb = sbase + B_OFF(s & 3);
        const int shift = dh * W_DIM + dw;

        uint32_t ra[2];
        #pragma unroll
        for (int mi = 0; mi < 2; mi++) {
            const bool ok = ((unsigned)(hh[mi] + dh) < (unsigned)H_DIM) &&
                            ((unsigned)(ww[mi] + dw) < (unsigned)W_DIM);
            ra[mi] = ok ? (Ab + (uint32_t)((pixloc[mi] + shift) * ROWB + khalf * 16))
                        : zaddr;
        }

        const uint32_t bb_base = Bb + (uint32_t)(wn * 2048 + lane * 16);
        #pragma unroll
        for (int ks = 0; ks < 2; ks++) {
            uint32_t a[2][4];
            ldmx4(a[0], ra[0] + ks * 32);
            ldmx4(a[1], ra[1] + ks * 32);
            uint32_t bb[4][4];
            #pragma unroll
            for (int q = 0; q < 4; q++)
                lds128(bb[q], bb_base + (uint32_t)(ks * 4096 + q * 512));
            #pragma unroll
            for (int q = 0; q < 4; q++)
                #pragma unroll
                for (int sb = 0; sb < 2; sb++) {
                    const int ni = q * 2 + sb;
                    #pragma unroll
                    for (int mi = 0; mi < 2; mi++)
                        mma_f16(acc[mi][ni], a[mi],
                                bb[q][sb * 2], bb[q][sb * 2 + 1]);
                }
        }

        if (++tap == 9) { tap = 0; cblk++; dh = -1; dw = -1; }
        else { if (++dw == 2) { dw = -1; dh++; } }
    }

    // ---- epilogue: +bias, scatter to NCHW ----
    #pragma unroll
    for (int mi = 0; mi < 2; mi++) {
        #pragma unroll
        for (int hf = 0; hf < 2; hf++) {
            const int m   = m_base + wm * 32 + mi * 16 + grp + 8 * hf;
            const int nn  = m / HW;
            const int phw = m - nn * HW;
            float* op = out + (size_t)nn * OC_DIM * HW + phw;
            #pragma unroll
            for (int ni = 0; ni < 8; ni++) {
                const int oc = oc_base + wn * 64 + ni * 8 + 2 * tig;
                const float b0 = __ldg(bias + oc);
                const float b1 = __ldg(bias + oc + 1);
                op[(size_t)oc * HW]       = acc[mi][ni][2 * hf + 0] + b0;
                op[(size_t)(oc + 1) * HW] = acc[mi][ni][2 * hf + 1] + b1;
            }
        }
    }
}

extern "C" void kernel_launch(void* const* d_in, const int* in_sizes, int n_in,
                              void* d_out, int out_size)
{
    const float* in   = (const float*)d_in[0];
    const float* wgt  = (const float*)d_in[1];
    const float* bias = (const float*)d_in[2];
    float* out        = (float*)d_out;

    prep_in_kernel<<<32 * 49, 256>>>(in);
    prep_w_kernel<<<(OC_DIM * K_TOTAL / 2) / 256, 256>>>(wgt);

    cudaFuncSetAttribute(conv2d_mma_kernel,
                         cudaFuncAttributeMaxDynamicSharedMemorySize, SMEM_TOTAL);
    dim3 grid(M_TOTAL / BM, OC_DIM / BN, 1);   // 784 x 2
    conv2d_mma_kernel<<<grid, THREADS, SMEM_TOTAL>>>(bias, out);
}

// round 16
// speedup vs baseline: 1.0670x; 1.0427x over previous
#include <cuda_runtime.h>
#include <cuda_fp16.h>
#include <cstdint>

// Conv2d 3x3 s1 p1 NCHW fp32: N=32,C=128,H=W=56,OC=256.
// Implicit GEMM mma.sync.m16n8k16 FP16 (fp32 accum). K' = cblk*288 + tap*32 + c.
// R16: main kernel = R12 (best measured, [pixel][256B] layout).
// prep_in v6: skewed smem transpose -> coalesced 512B stores into the
// SAME [pixel][256B] layout (skew sm[c][(p + 4*(c>>3)) & 63], stride 64).

#define N_IMG   32
#define C_IN    128
#define H_DIM   56
#define W_DIM   56
#define OC_DIM  256
#define HW      3136
#define CHW     (C_IN * HW)
#define K_TOTAL 1152
#define M_TOTAL 100352

#define BM 128
#define BN 128
#define THREADS 256
#define NSTAGES 36                       // 4 cblk * 9 taps

#define NPIX 248                         // 128 m + halo
#define ROWB 80                          // bytes per pixel row (64 data + 16 pad)
#define ABUF_BYTES (NPIX * ROWB)         // 19840
#define B_STAGE_BYTES 8192               // 128 oc x 32 k x 2B
#define A_OFF(i) ((i) * ABUF_BYTES)
#define B_OFF(j) (2 * ABUF_BYTES + (j) * B_STAGE_BYTES)
#define OFF_ZERO (2 * ABUF_BYTES + 4 * B_STAGE_BYTES)     // 72448
#define SMEM_TOTAL (OFF_ZERO + 64)       // 72512

// [pixel(M_TOTAL)][cblk(4)][t(4)][4 words] = pixel-major 256B rows
__device__ __align__(16) uint32_t g_in_h2[(size_t)M_TOTAL * 64];
__device__ __align__(16) uint32_t g_w_h[OC_DIM * K_TOTAL / 2];   // frag-order fp16x2

__device__ __forceinline__ uint32_t smem_u32(const void* p) {
    uint32_t a;
    asm("{ .reg .u64 t; cvta.to.shared.u64 t, %1; cvt.u32.u64 %0, t; }" : "=r"(a) : "l"(p));
    return a;
}
__device__ __forceinline__ uint32_t pack_h2(float lo, float hi) {
    __half2 h = __halves2half2(__float2half_rn(lo), __float2half_rn(hi));
    return *reinterpret_cast<uint32_t*>(&h);
}
__device__ __forceinline__ void cp16_zfill(uint32_t dst, const void* src, uint32_t sz) {
    asm volatile("cp.async.cg.shared.global [%0], [%1], 16, %2;"
                 :: "r"(dst), "l"(src), "r"(sz) : "memory");
}
__device__ __forceinline__ void cp16(uint32_t dst, const void* src) {
    asm volatile("cp.async.cg.shared.global [%0], [%1], 16;"
                 :: "r"(dst), "l"(src) : "memory");
}
__device__ __forceinline__ void lds128(uint32_t* r, uint32_t addr) {
    asm volatile("ld.shared.v4.u32 {%0,%1,%2,%3}, [%4];"
                 : "=r"(r[0]), "=r"(r[1]), "=r"(r[2]), "=r"(r[3]) : "r"(addr));
}
__device__ __forceinline__ void ldmx4(uint32_t* r, uint32_t addr) {
    asm volatile("ldmatrix.sync.aligned.m8n8.x4.shared.b16 {%0,%1,%2,%3}, [%4];"
                 : "=r"(r[0]), "=r"(r[1]), "=r"(r[2]), "=r"(r[3]) : "r"(addr));
}
__device__ __forceinline__ void mma_f16(float* c, const uint32_t* a,
                                        uint32_t b0, uint32_t b1) {
    asm volatile(
        "mma.sync.aligned.m16n8k16.row.col.f32.f16.f16.f32 "
        "{%0,%1,%2,%3}, {%4,%5,%6,%7}, {%8,%9}, {%0,%1,%2,%3};"
        : "+f"(c[0]), "+f"(c[1]), "+f"(c[2]), "+f"(c[3])
        : "r"(a[0]), "r"(a[1]), "r"(a[2]), "r"(a[3]), "r"(b0), "r"(b1));
}

// ---- prep v6: input NCHW fp32 -> [pixel][256B] fp16x2 (skewed transpose).
// Element (c, p) lives at sm[c][(p + 4*(c>>3)) & 63].
// Phase1: LDG.128 -> STS.128, conflict-free. Phase2: thread=(p, q-chunk),
// 8 LDS.32 (2-way conflict) + pack; warp STG = 512B contiguous.
__global__ void prep_in_kernel(const float* __restrict__ in) {
    __shared__ float sm[128][64];         // 32KB, skewed columns
    const int tid = threadIdx.x;
    const int n   = blockIdx.x / 49;
    const int hw0 = (blockIdx.x - n * 49) * 64;

    const float* src = in + (size_t)n * CHW + hw0;
    #pragma unroll
    for (int i = 0; i < 8; i++) {
        const int idx = tid + 256 * i;    // [0, 2048)
        const int c   = idx >> 4;
        const int f   = idx & 15;
        const float4 v = *(const float4*)(src + (size_t)c * HW + 4 * f);
        const int col = (4 * f + 4 * (c >> 3)) & 63;
        *(float4*)&sm[c][col] = v;
    }
    __syncthreads();

    #pragma unroll
    for (int i = 0; i < 4; i++) {
        const int idx2 = tid + 256 * i;   // [0, 1024) = 64 pixels x 16 chunks
        const int p = idx2 >> 4;          // pixel within tile
        const int q = idx2 & 15;          // 16B chunk within pixel (ch 8q..8q+7)
        const int col = (p + 4 * q) & 63; // skew: (c>>3) == q for c in [8q, 8q+8)
        uint32_t wds[4];
        #pragma unroll
        for (int e = 0; e < 4; e++)
            wds[e] = pack_h2(sm[8 * q + 2 * e][col], sm[8 * q + 2 * e + 1][col]);
        uint4* dst = (uint4*)(g_in_h2 + (size_t)(n * HW + hw0 + p) * 64 + q * 4);
        *dst = make_uint4(wds[0], wds[1], wds[2], wds[3]);
    }
}

// ---- prep: weights -> fp16x2 fragment order ----
// g_w_h layout: [s(36)][half(2)][ks(2)][wn(2)][q(4)][lane(32)][j(4)]
__global__ void prep_w_kernel(const float* __restrict__ wsrc) {
    const int idx  = blockIdx.x * blockDim.x + threadIdx.x;   // [0, 147456)
    const int s    = idx >> 12;
    const int w2   = idx & 4095;
    const int half = w2 >> 11;
    const int w    = w2 & 2047;
    const int ks   = w >> 10;
    const int wn   = (w >> 9) & 1;
    const int q    = (w >> 7) & 3;
    const int lane = (w >> 2) & 31;
    const int j    = w & 3;
    const int grp  = lane >> 2;
    const int tig  = lane & 3;
    const int oc   = half * 128 + wn * 64 + (2 * q + (j >> 1)) * 8 + grp;
    const int c0   = ks * 16 + (j & 1) * 8 + tig * 2;
    const int cblk = s / 9;
    const int rs   = s - 9 * cblk;
    const int ch   = cblk * 32 + c0;
    const float w0 = wsrc[(size_t)oc * K_TOTAL + ch * 9 + rs];
    const float w1 = wsrc[(size_t)oc * K_TOTAL + (ch + 1) * 9 + rs];
    g_w_h[idx] = pack_h2(w0, w1);
}

__global__ void __launch_bounds__(THREADS, 2)
conv2d_mma_kernel(const float* __restrict__ bias, float* __restrict__ out)
{
    extern __shared__ char smem_raw[];
    const uint32_t sbase = smem_u32(smem_raw);
    const uint32_t zaddr = sbase + OFF_ZERO;

    const int tid     = threadIdx.x;
    const int lane    = tid & 31;
    const int wid     = tid >> 5;
    const int m_base  = blockIdx.x * BM;
    const int nh      = blockIdx.y;            // oc half
    const int oc_base = nh * BN;

    if (tid < 16) ((uint32_t*)(smem_raw + OFF_ZERO))[tid] = 0u;

    // ---- A loader: 992 16B chunks (248 pixels x 4) ----
    auto load_A = [&](int cblk) {
        const uint32_t dbase = sbase + A_OFF(cblk & 1);
        #pragma unroll
        for (int j = 0; j < 4; j++) {
            const int ch_i = tid + 256 * j;
            if (ch_i >= NPIX * 4) break;
            const int pix = ch_i >> 2;
            const int t   = ch_i & 3;
            const int g   = m_base - 60 + pix;
            const bool ok = (g >= 0) && (g < M_TOTAL);
            const size_t gc = ok ? (size_t)g : 0;
            cp16_zfill(dbase + (uint32_t)(pix * ROWB + t * 16),
                       g_in_h2 + gc * 64 + cblk * 16 + t * 4,
                       ok ? 16u : 0u);
        }
    };
    auto load_B = [&](int s) {
        const uint32_t dst = sbase + B_OFF(s & 3) + (uint32_t)(tid * 16);
        const uint32_t* src = g_w_h + (size_t)s * 4096 + nh * 2048 + tid * 4;
        cp16(dst, src);
        cp16(dst + 4096, src + 1024);
    };

    // ---- compute mapping: 4(M) x 2(N) warps, warp tile 32x64 ----
    const int wm  = wid & 3;
    const int wn  = wid >> 2;
    const int grp = lane >> 2;
    const int tig = lane & 3;
    const int l15 = lane & 15;
    const int khalf = lane >> 4;

    int pixloc[2], hh[2], ww[2];
    #pragma unroll
    for (int mi = 0; mi < 2; mi++) {
        const int mrow = wm * 32 + mi * 16 + l15;
        pixloc[mi] = mrow + 60;
        const int m  = m_base + mrow;
        const int nn = m / HW;
        const int hw = m - nn * HW;
        hh[mi] = hw / W_DIM;
        ww[mi] = hw - hh[mi] * W_DIM;
    }

    float acc[2][8][4];
    #pragma unroll
    for (int mi = 0; mi < 2; mi++)
        #pragma unroll
        for (int ni = 0; ni < 8; ni++)
            #pragma unroll
            for (int q = 0; q < 4; q++) acc[mi][ni][q] = 0.0f;

    load_A(0); load_B(0);
    asm volatile("cp.async.commit_group;" ::: "memory");
    load_A(1); load_B(1);
    asm volatile("cp.async.commit_group;" ::: "memory");
    load_B(2);
    asm volatile("cp.async.commit_group;" ::: "memory");

    int tap = 0, cblk = 0, dh = -1, dw = -1;
    for (int s = 0; s < NSTAGES; s++) {
        asm volatile("cp.async.wait_group 2;" ::: "memory");
        __syncthreads();

        // issue next loads into the MMA shadow (buffers last read at s-1)
        if (s + 3 < NSTAGES) load_B(s + 3);
        if (tap == 0 && cblk < 3) load_A(cblk + 1);
        asm volatile("cp.async.commit_group;" ::: "memory");

        const uint32_t Ab = sbase + A_OFF(cblk & 1);
        const uint32_t Bb = sbase + B_OFF(s & 3);
        const int shift = dh * W_DIM + dw;

        uint32_t ra[2];
        #pragma unroll
        for (int mi = 0; mi < 2; mi++) {
            const bool ok = ((unsigned)(hh[mi] + dh) < (unsigned)H_DIM) &&
                            ((unsigned)(ww[mi] + dw) < (unsigned)W_DIM);
            ra[mi] = ok ? (Ab + (uint32_t)((pixloc[mi] + shift) * ROWB + khalf * 16))
                        : zaddr;
        }

        const uint32_t bb_base = Bb + (uint32_t)(wn * 2048 + lane * 16);
        #pragma unroll
        for (int ks = 0; ks < 2; ks++) {
            uint32_t a[2][4];
            ldmx4(a[0], ra[0] + ks * 32);
            ldmx4(a[1], ra[1] + ks * 32);
            uint32_t bb[4][4];
            #pragma unroll
            for (int q = 0; q < 4; q++)
                lds128(bb[q], bb_base + (uint32_t)(ks * 4096 + q * 512));
            #pragma unroll
            for (int q = 0; q < 4; q++)
                #pragma unroll
                for (int sb = 0; sb < 2; sb++) {
                    const int ni = q * 2 + sb;
                    #pragma unroll
                    for (int mi = 0; mi < 2; mi++)
                        mma_f16(acc[mi][ni], a[mi],
                                bb[q][sb * 2], bb[q][sb * 2 + 1]);
                }
        }

        if (++tap == 9) { tap = 0; cblk++; dh = -1; dw = -1; }
        else { if (++dw == 2) { dw = -1; dh++; } }
    }

    // ---- epilogue: +bias, scatter to NCHW ----
    #pragma unroll
    for (int mi = 0; mi < 2; mi++) {
        #pragma unroll
        for (int hf = 0; hf < 2; hf++) {
            const int m   = m_base + wm * 32 + mi * 16 + grp + 8 * hf;
            const int nn  = m / HW;
            const int phw = m - nn * HW;
            float* op = out + (size_t)nn * OC_DIM * HW + phw;
            #pragma unroll
            for (int ni = 0; ni < 8; ni++) {
                const int oc = oc_base + wn * 64 + ni * 8 + 2 * tig;
                const float b0 = __ldg(bias + oc);
                const float b1 = __ldg(bias + oc + 1);
                op[(size_t)oc * HW]       = acc[mi][ni][2 * hf + 0] + b0;
                op[(size_t)(oc + 1) * HW] = acc[mi][ni][2 * hf + 1] + b1;
            }
        }
    }
}

extern "C" void kernel_launch(void* const* d_in, const int* in_sizes, int n_in,
                              void* d_out, int out_size)
{
    const float* in   = (const float*)d_in[0];
    const float* wgt  = (const float*)d_in[1];
    const float* bias = (const float*)d_in[2];
    float* out        = (float*)d_out;

    prep_in_kernel<<<32 * 49, 256>>>(in);
    prep_w_kernel<<<(OC_DIM * K_TOTAL / 2) / 256, 256>>>(wgt);

    cudaFuncSetAttribute(conv2d_mma_kernel,
                         cudaFuncAttributeMaxDynamicSharedMemorySize, SMEM_TOTAL);
    dim3 grid(M_TOTAL / BM, OC_DIM / BN, 1);   // 784 x 2
    conv2d_mma_kernel<<<grid, THREADS, SMEM_TOTAL>>>(bias, out);
}

// round 17
// speedup vs baseline: 1.0935x; 1.0249x over previous
#include <cuda_runtime.h>
#include <cuda_fp16.h>
#include <cstdint>

// Conv2d 3x3 s1 p1 NCHW fp32: N=32,C=128,H=W=56,OC=256.
// Implicit GEMM mma.sync.m16n8k16 FP16 (fp32 accum). K' = cblk*288 + tap*32 + c.
// R17 (base R16): (1) full-stage fragment prefetch (all 12 LDS before the
// 128-MMA burst); (2) prep_in + prep_w merged into one launch.

#define N_IMG   32
#define C_IN    128
#define H_DIM   56
#define W_DIM   56
#define OC_DIM  256
#define HW      3136
#define CHW     (C_IN * HW)
#define K_TOTAL 1152
#define M_TOTAL 100352

#define BM 128
#define BN 128
#define THREADS 256
#define NSTAGES 36                       // 4 cblk * 9 taps

#define NPIX 248                         // 128 m + halo
#define ROWB 80                          // bytes per pixel row (64 data + 16 pad)
#define ABUF_BYTES (NPIX * ROWB)         // 19840
#define B_STAGE_BYTES 8192               // 128 oc x 32 k x 2B
#define A_OFF(i) ((i) * ABUF_BYTES)
#define B_OFF(j) (2 * ABUF_BYTES + (j) * B_STAGE_BYTES)
#define OFF_ZERO (2 * ABUF_BYTES + 4 * B_STAGE_BYTES)     // 72448
#define SMEM_TOTAL (OFF_ZERO + 64)       // 72512

#define PREP_IN_BLOCKS 1568
#define PREP_W_BLOCKS  576               // 147456 / 256

// [pixel(M_TOTAL)][cblk(4)][t(4)][4 words] = pixel-major 256B rows
__device__ __align__(16) uint32_t g_in_h2[(size_t)M_TOTAL * 64];
__device__ __align__(16) uint32_t g_w_h[OC_DIM * K_TOTAL / 2];   // frag-order fp16x2

__device__ __forceinline__ uint32_t smem_u32(const void* p) {
    uint32_t a;
    asm("{ .reg .u64 t; cvta.to.shared.u64 t, %1; cvt.u32.u64 %0, t; }" : "=r"(a) : "l"(p));
    return a;
}
__device__ __forceinline__ uint32_t pack_h2(float lo, float hi) {
    __half2 h = __halves2half2(__float2half_rn(lo), __float2half_rn(hi));
    return *reinterpret_cast<uint32_t*>(&h);
}
__device__ __forceinline__ void cp16_zfill(uint32_t dst, const void* src, uint32_t sz) {
    asm volatile("cp.async.cg.shared.global [%0], [%1], 16, %2;"
                 :: "r"(dst), "l"(src), "r"(sz) : "memory");
}
__device__ __forceinline__ void cp16(uint32_t dst, const void* src) {
    asm volatile("cp.async.cg.shared.global [%0], [%1], 16;"
                 :: "r"(dst), "l"(src) : "memory");
}
__device__ __forceinline__ void lds128(uint32_t* r, uint32_t addr) {
    asm volatile("ld.shared.v4.u32 {%0,%1,%2,%3}, [%4];"
                 : "=r"(r[0]), "=r"(r[1]), "=r"(r[2]), "=r"(r[3]) : "r"(addr));
}
__device__ __forceinline__ void ldmx4(uint32_t* r, uint32_t addr) {
    asm volatile("ldmatrix.sync.aligned.m8n8.x4.shared.b16 {%0,%1,%2,%3}, [%4];"
                 : "=r"(r[0]), "=r"(r[1]), "=r"(r[2]), "=r"(r[3]) : "r"(addr));
}
__device__ __forceinline__ void mma_f16(float* c, const uint32_t* a,
                                        uint32_t b0, uint32_t b1) {
    asm volatile(
        "mma.sync.aligned.m16n8k16.row.col.f32.f16.f16.f32 "
        "{%0,%1,%2,%3}, {%4,%5,%6,%7}, {%8,%9}, {%0,%1,%2,%3};"
        : "+f"(c[0]), "+f"(c[1]), "+f"(c[2]), "+f"(c[3])
        : "r"(a[0]), "r"(a[1]), "r"(a[2]), "r"(a[3]), "r"(b0), "r"(b1));
}

// ---- merged prep: blocks [0,1568) transpose input; [1568, 2144) transform W.
__global__ void prep_kernel(const float* __restrict__ in,
                            const float* __restrict__ wsrc) {
    __shared__ float sm[128][64];
    const int tid = threadIdx.x;

    if (blockIdx.x < PREP_IN_BLOCKS) {
        // --- input transpose (skewed smem; coalesced 512B stores) ---
        const int n   = blockIdx.x / 49;
        const int hw0 = (blockIdx.x - n * 49) * 64;
        const float* src = in + (size_t)n * CHW + hw0;
        #pragma unroll
        for (int i = 0; i < 8; i++) {
            const int idx = tid + 256 * i;
            const int c   = idx >> 4;
            const int f   = idx & 15;
            const float4 v = *(const float4*)(src + (size_t)c * HW + 4 * f);
            const int col = (4 * f + 4 * (c >> 3)) & 63;
            *(float4*)&sm[c][col] = v;
        }
        __syncthreads();
        #pragma unroll
        for (int i = 0; i < 4; i++) {
            const int idx2 = tid + 256 * i;
            const int p = idx2 >> 4;
            const int q = idx2 & 15;
            const int col = (p + 4 * q) & 63;
            uint32_t wds[4];
            #pragma unroll
            for (int e = 0; e < 4; e++)
                wds[e] = pack_h2(sm[8 * q + 2 * e][col], sm[8 * q + 2 * e + 1][col]);
            uint4* dst = (uint4*)(g_in_h2 + (size_t)(n * HW + hw0 + p) * 64 + q * 4);
            *dst = make_uint4(wds[0], wds[1], wds[2], wds[3]);
        }
    } else {
        // --- weights -> fp16x2 fragment order ---
        // g_w_h layout: [s(36)][half(2)][ks(2)][wn(2)][q(4)][lane(32)][j(4)]
        const int idx  = (blockIdx.x - PREP_IN_BLOCKS) * 256 + tid;
        const int s    = idx >> 12;
        const int w2   = idx & 4095;
        const int half = w2 >> 11;
        const int w    = w2 & 2047;
        const int ks   = w >> 10;
        const int wn   = (w >> 9) & 1;
        const int q    = (w >> 7) & 3;
        const int lane = (w >> 2) & 31;
        const int j    = w & 3;
        const int grp  = lane >> 2;
        const int tig  = lane & 3;
        const int oc   = half * 128 + wn * 64 + (2 * q + (j >> 1)) * 8 + grp;
        const int c0   = ks * 16 + (j & 1) * 8 + tig * 2;
        const int cblk = s / 9;
        const int rs   = s - 9 * cblk;
        const int ch   = cblk * 32 + c0;
        const float w0 = wsrc[(size_t)oc * K_TOTAL + ch * 9 + rs];
        const float w1 = wsrc[(size_t)oc * K_TOTAL + (ch + 1) * 9 + rs];
        g_w_h[idx] = pack_h2(w0, w1);
    }
}

__global__ void __launch_bounds__(THREADS, 2)
conv2d_mma_kernel(const float* __restrict__ bias, float* __restrict__ out)
{
    extern __shared__ char smem_raw[];
    const uint32_t sbase = smem_u32(smem_raw);
    const uint32_t zaddr = sbase + OFF_ZERO;

    const int tid     = threadIdx.x;
    const int lane    = tid & 31;
    const int wid     = tid >> 5;
    const int m_base  = blockIdx.x * BM;
    const int nh      = blockIdx.y;            // oc half
    const int oc_base = nh * BN;

    if (tid < 16) ((uint32_t*)(smem_raw + OFF_ZERO))[tid] = 0u;

    // ---- A loader: 992 16B chunks (248 pixels x 4) ----
    auto load_A = [&](int cblk) {
        const uint32_t dbase = sbase + A_OFF(cblk & 1);
        #pragma unroll
        for (int j = 0; j < 4; j++) {
            const int ch_i = tid + 256 * j;
            if (ch_i >= NPIX * 4) break;
            const int pix = ch_i >> 2;
            const int t   = ch_i & 3;
            const int g   = m_base - 60 + pix;
            const bool ok = (g >= 0) && (g < M_TOTAL);
            const size_t gc = ok ? (size_t)g : 0;
            cp16_zfill(dbase + (uint32_t)(pix * ROWB + t * 16),
                       g_in_h2 + gc * 64 + cblk * 16 + t * 4,
                       ok ? 16u : 0u);
        }
    };
    auto load_B = [&](int s) {
        const uint32_t dst = sbase + B_OFF(s & 3) + (uint32_t)(tid * 16);
        const uint32_t* src = g_w_h + (size_t)s * 4096 + nh * 2048 + tid * 4;
        cp16(dst, src);
        cp16(dst + 4096, src + 1024);
    };

    // ---- compute mapping: 4(M) x 2(N) warps, warp tile 32x64 ----
    const int wm  = wid & 3;
    const int wn  = wid >> 2;
    const int grp = lane >> 2;
    const int tig = lane & 3;
    const int l15 = lane & 15;
    const int khalf = lane >> 4;

    int pixloc[2], hh[2], ww[2];
    #pragma unroll
    for (int mi = 0; mi < 2; mi++) {
        const int mrow = wm * 32 + mi * 16 + l15;
        pixloc[mi] = mrow + 60;
        const int m  = m_base + mrow;
        const int nn = m / HW;
        const int hw = m - nn * HW;
        hh[mi] = hw / W_DIM;
        ww[mi] = hw - hh[mi] * W_DIM;
    }

    float acc[2][8][4];
    #pragma unroll
    for (int mi = 0; mi < 2; mi++)
        #pragma unroll
        for (int ni = 0; ni < 8; ni++)
            #pragma unroll
            for (int q = 0; q < 4; q++) acc[mi][ni][q] = 0.0f;

    load_A(0); load_B(0);
    asm volatile("cp.async.commit_group;" ::: "memory");
    load_A(1); load_B(1);
    asm volatile("cp.async.commit_group;" ::: "memory");
    load_B(2);
    asm volatile("cp.async.commit_group;" ::: "memory");

    int tap = 0, cblk = 0, dh = -1, dw = -1;
    for (int s = 0; s < NSTAGES; s++) {
        asm volatile("cp.async.wait_group 2;" ::: "memory");
        __syncthreads();

        // issue next loads into the MMA shadow (buffers last read at s-1)
        if (s + 3 < NSTAGES) load_B(s + 3);
        if (tap == 0 && cblk < 3) load_A(cblk + 1);
        asm volatile("cp.async.commit_group;" ::: "memory");

        const uint32_t Ab = sbase + A_OFF(cblk & 1);
        const uint32_t Bb = sbase + B_OFF(s & 3);
        const int shift = dh * W_DIM + dw;

        uint32_t ra[2];
        #pragma unroll
        for (int mi = 0; mi < 2; mi++) {
            const bool ok = ((unsigned)(hh[mi] + dh) < (unsigned)H_DIM) &&
                            ((unsigned)(ww[mi] + dw) < (unsigned)W_DIM);
            ra[mi] = ok ? (Ab + (uint32_t)((pixloc[mi] + shift) * ROWB + khalf * 16))
                        : zaddr;
        }

        // ---- full-stage fragment prefetch: all 12 LDS, then 128 MMAs ----
        const uint32_t bb_base = Bb + (uint32_t)(wn * 2048 + lane * 16);
        uint32_t a[2][2][4];     // [ks][mi][regs]
        uint32_t bb[2][4][4];    // [ks][q][regs]
        #pragma unroll
        for (int ks = 0; ks < 2; ks++) {
            ldmx4(a[ks][0], ra[0] + ks * 32);
            ldmx4(a[ks][1], ra[1] + ks * 32);
            #pragma unroll
            for (int q = 0; q < 4; q++)
                lds128(bb[ks][q], bb_base + (uint32_t)(ks * 4096 + q * 512));
        }
        #pragma unroll
        for (int ks = 0; ks < 2; ks++)
            #pragma unroll
            for (int q = 0; q < 4; q++)
                #pragma unroll
                for (int sb = 0; sb < 2; sb++) {
                    const int ni = q * 2 + sb;
                    #pragma unroll
                    for (int mi = 0; mi < 2; mi++)
                        mma_f16(acc[mi][ni], a[ks][mi],
                                bb[ks][q][sb * 2], bb[ks][q][sb * 2 + 1]);
                }

        if (++tap == 9) { tap = 0; cblk++; dh = -1; dw = -1; }
        else { if (++dw == 2) { dw = -1; dh++; } }
    }

    // ---- epilogue: +bias, scatter to NCHW ----
    #pragma unroll
    for (int mi = 0; mi < 2; mi++) {
        #pragma unroll
        for (int hf = 0; hf < 2; hf++) {
            const int m   = m_base + wm * 32 + mi * 16 + grp + 8 * hf;
            const int nn  = m / HW;
            const int phw = m - nn * HW;
            float* op = out + (size_t)nn * OC_DIM * HW + phw;
            #pragma unroll
            for (int ni = 0; ni < 8; ni++) {
                const int oc = oc_base + wn * 64 + ni * 8 + 2 * tig;
                const float b0 = __ldg(bias + oc);
                const float b1 = __ldg(bias + oc + 1);
                op[(size_t)oc * HW]       = acc[mi][ni][2 * hf + 0] + b0;
                op[(size_t)(oc + 1) * HW] = acc[mi][ni][2 * hf + 1] + b1;
            }
        }
    }
}

extern "C" void kernel_launch(void* const* d_in, const int* in_sizes, int n_in,
                              void* d_out, int out_size)
{
    const float* in   = (const float*)d_in[0];
    const float* wgt  = (const float*)d_in[1];
    const float* bias = (const float*)d_in[2];
    float* out        = (float*)d_out;

    prep_kernel<<<PREP_IN_BLOCKS + PREP_W_BLOCKS, 256>>>(in, wgt);

    cudaFuncSetAttribute(conv2d_mma_kernel,
                         cudaFuncAttributeMaxDynamicSharedMemorySize, SMEM_TOTAL);
    dim3 grid(M_TOTAL / BM, OC_DIM / BN, 1);   // 784 x 2
    conv2d_mma_kernel<<<grid, THREADS, SMEM_TOTAL>>>(bias, out);
}